// round 15
// baseline (speedup 1.0000x reference)
#include <cuda_runtime.h>

#define FULL 0xffffffffu

// One warp per batch element, 8 warps/block.
// Lanes 0-15 own the A row, lanes 16-31 the B row.
// Per-nibble vectors live in PERMUTED lane order (lane owns value index
// cL(s) low / cH(s) high — the reduce-scatter's natural output); rotations
// use per-lane-constant shuffle sources via cL^-1 = cH.
// Input softmax normalization is DEFERRED past the conv (exact identity).
// Conv runs as 4 parallel rotation chains (rotate-by-4) to cut serial depth.
// Next byte's rows are prefetched to L2 (1 MIO op/iter, zero registers).
// Per-warp smem (64 floats): [0..15] pbL, [16..31] pbH, [32..63] out staging.
__global__ void __launch_bounds__(256, 7) nalu_kernel(
        const float* __restrict__ A, const float* __restrict__ Bq,
        float* __restrict__ O, int B) {
    __shared__ float smem[8][64];
    const int lane = threadIdx.x & 31;
    const int n = blockIdx.x * 8 + (threadIdx.x >> 5);
    if (n >= B) return;
    float* ws = smem[threadIdx.x >> 5];

    const bool lo   = lane < 16;
    const int  l15  = lane & 15;
    const int  hi16 = lane & 16;
    const bool b0 = lane & 1, b1 = lane & 2, b2 = lane & 4, b3 = lane & 8;
    // value indices owned after reduce-scatter
    const int cLv = ((l15 >> 3) & 1) | (((l15 >> 2) & 1) << 1) | ((l15 & 1) << 2) | (((l15 >> 1) & 1) << 3);
    const int cHv = ((l15 >> 2) & 1) | (((l15 >> 3) & 1) << 1) | (((l15 >> 1) & 1) << 2) | ((l15 & 1) << 3);
    const int kk  = lo ? cLv : cHv;          // this lane's value index in its half
    // lane-owning-value maps (inverse perms): lower F_L, upper F_H
#define F_L(t) (((t) >> 2) & 1) | ((((t) >> 3) & 1) << 1) | ((((t) >> 1) & 1) << 2) | (((t) & 1) << 3)
#define F_H(t) (((t) >> 3) & 1) | ((((t) >> 2) & 1) << 1) | (((t) & 1) << 2) | ((((t) >> 1) & 1) << 3)
    const int km1 = (kk - 1) & 15;
    const int km4 = (kk - 4) & 15;
    const int srcRot1 = (lo ? (F_L(km1)) : (F_H(km1))) | hi16;  // value rot-down-1
    const int srcRot4 = (lo ? (F_L(km4)) : (F_H(km4))) | hi16;  // value rot-down-4
#undef F_L
#undef F_H

    // smem addresses
    float* stPBL = ws + cLv;            // upper lanes: raw-exp pbL (value order)
    float* stPBH = ws + 16 + cHv;       // upper lanes: raw-exp pbH
    float* stOut = ws + 32 + kk + (lo ? 0 : 16);
    const float4* pbP = (const float4*)(ws + (lo ? 0 : 16));
    const int lb = (lane & 1) * 8;
    const float4* po4 = (const float4*)(ws + 32 + lb);
    const float*  pshp = ws + 48 + (lane >> 1);

    const float4* rowbase = (const float4*)((lo ? A : Bq) + (size_t)n * 1024);
    float* orow = O + (size_t)n * 1024 + lane * 8;

    float c1 = 0.f;  // P(carry=1); carry starts one-hot [1,0]

#pragma unroll 1
    for (int i = 0; i < 4; i++) {
        const float4* r4 = rowbase + i * 64;
        float4 av0 = r4[l15];
        float4 av1 = r4[16 + l15];
        float4 av2 = r4[32 + l15];
        float4 av3 = r4[48 + l15];

        // ---- prefetch next byte's row to L2 (16 lanes x 64B = 1KB/stream) ----
        {
            int ipf = (i < 3) ? i + 1 : i;
            const char* pfa = (const char*)(rowbase + ipf * 64) + l15 * 64;
            asm volatile("prefetch.global.L2 [%0];" :: "l"(pfa));
        }

        // ---- low-nibble sums via reduce-scatter (lane owns la[cLv]) ----
        float la0 = (av0.x + av1.x) + (av2.x + av3.x);
        float la1 = (av0.y + av1.y) + (av2.y + av3.y);
        float la2 = (av0.z + av1.z) + (av2.z + av3.z);
        float la3 = (av0.w + av1.w) + (av2.w + av3.w);
        float w0 = (b2 ? la2 : la0) + __shfl_xor_sync(FULL, b2 ? la0 : la2, 4);
        float w1 = (b2 ? la3 : la1) + __shfl_xor_sync(FULL, b2 ? la1 : la3, 4);
        float lres = (b3 ? w1 : w0) + __shfl_xor_sync(FULL, b3 ? w0 : w1, 8);

        // ---- high-nibble sums via reduce-scatter (lane owns ha[cHv]) ----
        float hp0 = (av0.x + av0.y) + (av0.z + av0.w);
        float hp1 = (av1.x + av1.y) + (av1.z + av1.w);
        float hp2 = (av2.x + av2.y) + (av2.z + av2.w);
        float hp3 = (av3.x + av3.y) + (av3.z + av3.w);
        float z0 = (b0 ? hp2 : hp0) + __shfl_xor_sync(FULL, b0 ? hp0 : hp2, 1);
        float z1 = (b0 ? hp3 : hp1) + __shfl_xor_sync(FULL, b0 ? hp1 : hp3, 1);
        float hres = (b1 ? z1 : z0) + __shfl_xor_sync(FULL, b1 ? z0 : z1, 2);

        // ---- packed-bf16 group max (exact: shift-invariance of softmax) ----
        unsigned m = (__float_as_uint(hres) & 0xFFFF0000u) | (__float_as_uint(lres) >> 16);
        m = __vmaxu2(m, __shfl_xor_sync(FULL, m, 1));
        m = __vmaxu2(m, __shfl_xor_sync(FULL, m, 2));
        m = __vmaxu2(m, __shfl_xor_sync(FULL, m, 4));
        m = __vmaxu2(m, __shfl_xor_sync(FULL, m, 8));
        float mh = __uint_as_float(m & 0xFFFF0000u);
        float ml = __uint_as_float(m << 16);
        // raw (unnormalized) exps — normalization deferred past the conv
        float eh = __expf(100.f * (hres - mh));   // paH|pbH value at index cHv
        float el = __expf(100.f * (lres - ml));   // paL|pbL value at index cLv

        // ---- stage pb tables (upper half) in value order ----
        if (!lo) {
            *stPBL = el;
            *stPBH = eh;
        }
        // q0: lower lane -> paL[kk], upper lane -> paH[kk]
        float qshf = __shfl_sync(FULL, eh, l15);
        float q0   = lo ? el : qshf;
        __syncwarp();

        // ---- merged cyclic convs, 4 rotation chains (L lower, H upper) ----
        // chain c handles taps j = c, c+4, c+8, c+12 with start pa[kk-c];
        // all chains rotate by 4 per step. pb taps: uniform LDS.128, one
        // float4 live per step.
        float q1 = __shfl_sync(FULL, q0, srcRot1);   // pa[kk-1]
        float q2 = __shfl_sync(FULL, q1, srcRot1);   // pa[kk-2]
        float q3 = __shfl_sync(FULL, q2, srcRot1);   // pa[kk-3]
        float u1a, u2a = 0.f, u1b = 0.f, u2b = 0.f;  // u1: j<=kk, u2: wrap
        {
            float4 pb = pbP[0];
            u1a = q0 * pb.x;                                       // j=0
            if (1 <= kk) u1a = fmaf(q1, pb.y, u1a); else u2a = fmaf(q1, pb.y, u2a);
            if (2 <= kk) u1b = fmaf(q2, pb.z, u1b); else u2b = fmaf(q2, pb.z, u2b);
            if (3 <= kk) u1b = fmaf(q3, pb.w, u1b); else u2b = fmaf(q3, pb.w, u2b);
        }
#pragma unroll
        for (int t = 1; t < 4; t++) {
            q0 = __shfl_sync(FULL, q0, srcRot4);
            q1 = __shfl_sync(FULL, q1, srcRot4);
            q2 = __shfl_sync(FULL, q2, srcRot4);
            q3 = __shfl_sync(FULL, q3, srcRot4);
            float4 pb = pbP[t];
            int j = 4 * t;
            if (j     <= kk) u1a = fmaf(q0, pb.x, u1a); else u2a = fmaf(q0, pb.x, u2a);
            if (j + 1 <= kk) u1a = fmaf(q1, pb.y, u1a); else u2a = fmaf(q1, pb.y, u2a);
            if (j + 2 <= kk) u1b = fmaf(q2, pb.z, u1b); else u2b = fmaf(q2, pb.z, u2b);
            if (j + 3 <= kk) u1b = fmaf(q3, pb.w, u1b); else u2b = fmaf(q3, pb.w, u2b);
        }
        float u2 = u2a + u2b;
        float u  = (u1a + u1b) + u2;

        // ---- per-half reductions: r0 = sum u2 (wrap mass), S = sum u ----
        float r0 = u2, S = u;
        r0 += __shfl_xor_sync(FULL, r0, 1);  S += __shfl_xor_sync(FULL, S, 1);
        r0 += __shfl_xor_sync(FULL, r0, 2);  S += __shfl_xor_sync(FULL, S, 2);
        r0 += __shfl_xor_sync(FULL, r0, 4);  S += __shfl_xor_sync(FULL, S, 4);
        r0 += __shfl_xor_sync(FULL, r0, 8);  S += __shfl_xor_sync(FULL, S, 8);
        float r0o = __shfl_xor_sync(FULL, r0, 16);
        float So  = __shfl_xor_sync(FULL, S, 16);
        float r0L = lo ? r0 : r0o,  r0H = lo ? r0o : r0;
        float SL  = lo ? S  : So,   SH  = lo ? So  : S;

        float v    = __shfl_sync(FULL, u, srcRot1);   // u[(kk-1)&15] per half
        float u15L = __shfl_sync(FULL, u, 15);        // lane 15 owns value 15
        float u15H = __shfl_sync(FULL, u, 31);

        // ---- serial carry chain (lane-uniform; normalized by S) ----
        float pc1L = __fdividef(1.f, 1.f + __expf(100.f * (1.f - 2.f * c1)));
        float pc0L = 1.f - pc1L;
        c1 = __fdividef(fmaf(pc0L, r0L, pc1L * (r0L + u15L)), SL);
        float pc1H = __fdividef(1.f, 1.f + __expf(100.f * (1.f - 2.f * c1)));
        float pc0H = 1.f - pc1H;
        c1 = __fdividef(fmaf(pc0H, r0H, pc1H * (r0H + u15H)), SH);

        // per-half blended sums, normalized by own-half S
        float pca = lo ? pc0L : pc0H;
        float pcb = lo ? pc1L : pc1H;
        float x = __fdividef(fmaf(pca, u, pcb * v), S);

        // ---- output softmax (permutation-invariant) ----
        float mo = x;
        mo = fmaxf(mo, __shfl_xor_sync(FULL, mo, 1));
        mo = fmaxf(mo, __shfl_xor_sync(FULL, mo, 2));
        mo = fmaxf(mo, __shfl_xor_sync(FULL, mo, 4));
        mo = fmaxf(mo, __shfl_xor_sync(FULL, mo, 8));
        float eo = __expf(100.f * (x - mo));
        float so = eo;
        so += __shfl_xor_sync(FULL, so, 1);
        so += __shfl_xor_sync(FULL, so, 2);
        so += __shfl_xor_sync(FULL, so, 4);
        so += __shfl_xor_sync(FULL, so, 8);
        float p_out = __fdividef(eo, so);

        // ---- outer product via smem (store in value order) ----
        *stOut = p_out;              // [32..47]=psl, [48..63]=psh (natural order)
        __syncwarp();
        float4 o0 = po4[0];
        float4 o1 = po4[1];
        float hvv = *pshp;           // psh[lane>>1]
        o0.x *= hvv;  o0.y *= hvv;  o0.z *= hvv;  o0.w *= hvv;
        o1.x *= hvv;  o1.y *= hvv;  o1.z *= hvv;  o1.w *= hvv;
        ((float4*)(orow + i * 256))[0] = o0;
        ((float4*)(orow + i * 256))[1] = o1;
    }
}

extern "C" void kernel_launch(void* const* d_in, const int* in_sizes, int n_in,
                              void* d_out, int out_size) {
    const float* A  = (const float*)d_in[0];
    const float* Bq = (const float*)d_in[1];
    float* O = (float*)d_out;
    int B = in_sizes[0] / 1024;          // [B, 4, 256]
    dim3 grid((B + 7) / 8);
    nalu_kernel<<<grid, 256>>>(A, Bq, O, B);
}

// round 16
// speedup vs baseline: 1.0107x; 1.0107x over previous
#include <cuda_runtime.h>

#define FULL 0xffffffffu

// One warp per batch element, 8 warps/block.
// Lanes 0-15 own the A row, lanes 16-31 the B row.
// Per-nibble vectors live in PERMUTED lane order (lane owns value index
// cL(s) low / cH(s) high — the reduce-scatter's natural output); rotations
// use per-lane-constant shuffle sources via cL^-1 = cH.
// Input softmax normalization is DEFERRED past the conv (exact identity).
// Conv runs as 4 parallel rotation chains (rotate-by-4) to cut serial depth.
// Output softmax needs no max reduction: its logits are provably in [0,1],
// so a constant 0.5 shift bounds the exp range (shift-invariance = exact).
// Per-warp smem (64 floats): [0..15] pbL, [16..31] pbH, [32..63] out staging.
__global__ void __launch_bounds__(256, 7) nalu_kernel(
        const float* __restrict__ A, const float* __restrict__ Bq,
        float* __restrict__ O, int B) {
    __shared__ float smem[8][64];
    const int lane = threadIdx.x & 31;
    const int n = blockIdx.x * 8 + (threadIdx.x >> 5);
    if (n >= B) return;
    float* ws = smem[threadIdx.x >> 5];

    const bool lo   = lane < 16;
    const int  l15  = lane & 15;
    const int  hi16 = lane & 16;
    const bool b0 = lane & 1, b1 = lane & 2, b2 = lane & 4, b3 = lane & 8;
    // value indices owned after reduce-scatter
    const int cLv = ((l15 >> 3) & 1) | (((l15 >> 2) & 1) << 1) | ((l15 & 1) << 2) | (((l15 >> 1) & 1) << 3);
    const int cHv = ((l15 >> 2) & 1) | (((l15 >> 3) & 1) << 1) | (((l15 >> 1) & 1) << 2) | ((l15 & 1) << 3);
    const int kk  = lo ? cLv : cHv;          // this lane's value index in its half
    // lane-owning-value maps (inverse perms): lower F_L, upper F_H
#define F_L(t) (((t) >> 2) & 1) | ((((t) >> 3) & 1) << 1) | ((((t) >> 1) & 1) << 2) | (((t) & 1) << 3)
#define F_H(t) (((t) >> 3) & 1) | ((((t) >> 2) & 1) << 1) | (((t) & 1) << 2) | ((((t) >> 1) & 1) << 3)
    const int km1 = (kk - 1) & 15;
    const int km4 = (kk - 4) & 15;
    const int srcRot1 = (lo ? (F_L(km1)) : (F_H(km1))) | hi16;  // value rot-down-1
    const int srcRot4 = (lo ? (F_L(km4)) : (F_H(km4))) | hi16;  // value rot-down-4
#undef F_L
#undef F_H

    // smem addresses
    float* stPBL = ws + cLv;            // upper lanes: raw-exp pbL (value order)
    float* stPBH = ws + 16 + cHv;       // upper lanes: raw-exp pbH
    float* stOut = ws + 32 + kk + (lo ? 0 : 16);
    const float4* pbP = (const float4*)(ws + (lo ? 0 : 16));
    const int lb = (lane & 1) * 8;
    const float4* po4 = (const float4*)(ws + 32 + lb);
    const float*  pshp = ws + 48 + (lane >> 1);

    const float4* rowbase = (const float4*)((lo ? A : Bq) + (size_t)n * 1024);
    float* orow = O + (size_t)n * 1024 + lane * 8;

    float c1 = 0.f;  // P(carry=1); carry starts one-hot [1,0]

#pragma unroll 1
    for (int i = 0; i < 4; i++) {
        const float4* r4 = rowbase + i * 64;
        float4 av0 = r4[l15];
        float4 av1 = r4[16 + l15];
        float4 av2 = r4[32 + l15];
        float4 av3 = r4[48 + l15];

        // ---- low-nibble sums via reduce-scatter (lane owns la[cLv]) ----
        float la0 = (av0.x + av1.x) + (av2.x + av3.x);
        float la1 = (av0.y + av1.y) + (av2.y + av3.y);
        float la2 = (av0.z + av1.z) + (av2.z + av3.z);
        float la3 = (av0.w + av1.w) + (av2.w + av3.w);
        float w0 = (b2 ? la2 : la0) + __shfl_xor_sync(FULL, b2 ? la0 : la2, 4);
        float w1 = (b2 ? la3 : la1) + __shfl_xor_sync(FULL, b2 ? la1 : la3, 4);
        float lres = (b3 ? w1 : w0) + __shfl_xor_sync(FULL, b3 ? w0 : w1, 8);

        // ---- high-nibble sums via reduce-scatter (lane owns ha[cHv]) ----
        float hp0 = (av0.x + av0.y) + (av0.z + av0.w);
        float hp1 = (av1.x + av1.y) + (av1.z + av1.w);
        float hp2 = (av2.x + av2.y) + (av2.z + av2.w);
        float hp3 = (av3.x + av3.y) + (av3.z + av3.w);
        float z0 = (b0 ? hp2 : hp0) + __shfl_xor_sync(FULL, b0 ? hp0 : hp2, 1);
        float z1 = (b0 ? hp3 : hp1) + __shfl_xor_sync(FULL, b0 ? hp1 : hp3, 1);
        float hres = (b1 ? z1 : z0) + __shfl_xor_sync(FULL, b1 ? z0 : z1, 2);

        // ---- packed-bf16 group max (exact: shift-invariance of softmax) ----
        unsigned m = (__float_as_uint(hres) & 0xFFFF0000u) | (__float_as_uint(lres) >> 16);
        m = __vmaxu2(m, __shfl_xor_sync(FULL, m, 1));
        m = __vmaxu2(m, __shfl_xor_sync(FULL, m, 2));
        m = __vmaxu2(m, __shfl_xor_sync(FULL, m, 4));
        m = __vmaxu2(m, __shfl_xor_sync(FULL, m, 8));
        float mh = __uint_as_float(m & 0xFFFF0000u);
        float ml = __uint_as_float(m << 16);
        // raw (unnormalized) exps — normalization deferred past the conv
        float eh = __expf(100.f * (hres - mh));   // paH|pbH value at index cHv
        float el = __expf(100.f * (lres - ml));   // paL|pbL value at index cLv

        // ---- stage pb tables (upper half) in value order ----
        if (!lo) {
            *stPBL = el;
            *stPBH = eh;
        }
        // q0: lower lane -> paL[kk], upper lane -> paH[kk]
        float qshf = __shfl_sync(FULL, eh, l15);
        float q0   = lo ? el : qshf;
        __syncwarp();

        // ---- merged cyclic convs, 4 rotation chains (L lower, H upper) ----
        // chain c handles taps j = c, c+4, c+8, c+12 with start pa[kk-c];
        // all chains rotate by 4 per step. pb taps: uniform LDS.128, one
        // float4 live per step.
        float q1 = __shfl_sync(FULL, q0, srcRot1);   // pa[kk-1]
        float q2 = __shfl_sync(FULL, q1, srcRot1);   // pa[kk-2]
        float q3 = __shfl_sync(FULL, q2, srcRot1);   // pa[kk-3]
        float u1a, u2a = 0.f, u1b = 0.f, u2b = 0.f;  // u1: j<=kk, u2: wrap
        {
            float4 pb = pbP[0];
            u1a = q0 * pb.x;                                       // j=0
            if (1 <= kk) u1a = fmaf(q1, pb.y, u1a); else u2a = fmaf(q1, pb.y, u2a);
            if (2 <= kk) u1b = fmaf(q2, pb.z, u1b); else u2b = fmaf(q2, pb.z, u2b);
            if (3 <= kk) u1b = fmaf(q3, pb.w, u1b); else u2b = fmaf(q3, pb.w, u2b);
        }
#pragma unroll
        for (int t = 1; t < 4; t++) {
            q0 = __shfl_sync(FULL, q0, srcRot4);
            q1 = __shfl_sync(FULL, q1, srcRot4);
            q2 = __shfl_sync(FULL, q2, srcRot4);
            q3 = __shfl_sync(FULL, q3, srcRot4);
            float4 pb = pbP[t];
            int j = 4 * t;
            if (j     <= kk) u1a = fmaf(q0, pb.x, u1a); else u2a = fmaf(q0, pb.x, u2a);
            if (j + 1 <= kk) u1a = fmaf(q1, pb.y, u1a); else u2a = fmaf(q1, pb.y, u2a);
            if (j + 2 <= kk) u1b = fmaf(q2, pb.z, u1b); else u2b = fmaf(q2, pb.z, u2b);
            if (j + 3 <= kk) u1b = fmaf(q3, pb.w, u1b); else u2b = fmaf(q3, pb.w, u2b);
        }
        float u2 = u2a + u2b;
        float u  = (u1a + u1b) + u2;

        // ---- per-half reductions: r0 = sum u2 (wrap mass), S = sum u ----
        float r0 = u2, S = u;
        r0 += __shfl_xor_sync(FULL, r0, 1);  S += __shfl_xor_sync(FULL, S, 1);
        r0 += __shfl_xor_sync(FULL, r0, 2);  S += __shfl_xor_sync(FULL, S, 2);
        r0 += __shfl_xor_sync(FULL, r0, 4);  S += __shfl_xor_sync(FULL, S, 4);
        r0 += __shfl_xor_sync(FULL, r0, 8);  S += __shfl_xor_sync(FULL, S, 8);
        float r0o = __shfl_xor_sync(FULL, r0, 16);
        float So  = __shfl_xor_sync(FULL, S, 16);
        float r0L = lo ? r0 : r0o,  r0H = lo ? r0o : r0;
        float SL  = lo ? S  : So,   SH  = lo ? So  : S;

        float v    = __shfl_sync(FULL, u, srcRot1);   // u[(kk-1)&15] per half
        float u15L = __shfl_sync(FULL, u, 15);        // lane 15 owns value 15
        float u15H = __shfl_sync(FULL, u, 31);

        // ---- serial carry chain (lane-uniform; normalized by S) ----
        float pc1L = __fdividef(1.f, 1.f + __expf(100.f * (1.f - 2.f * c1)));
        float pc0L = 1.f - pc1L;
        c1 = __fdividef(fmaf(pc0L, r0L, pc1L * (r0L + u15L)), SL);
        float pc1H = __fdividef(1.f, 1.f + __expf(100.f * (1.f - 2.f * c1)));
        float pc0H = 1.f - pc1H;
        c1 = __fdividef(fmaf(pc0H, r0H, pc1H * (r0H + u15H)), SH);

        // per-half blended sums, normalized by own-half S
        float pca = lo ? pc0L : pc0H;
        float pcb = lo ? pc1L : pc1H;
        float x = __fdividef(fmaf(pca, u, pcb * v), S);

        // ---- output softmax: x in [0,1] by construction, so a constant 0.5
        //      shift is range-safe (exp in [e^-50, e^50]); no max reduction ----
        float eo = __expf(100.f * (x - 0.5f));
        float so = eo;
        so += __shfl_xor_sync(FULL, so, 1);
        so += __shfl_xor_sync(FULL, so, 2);
        so += __shfl_xor_sync(FULL, so, 4);
        so += __shfl_xor_sync(FULL, so, 8);
        float p_out = __fdividef(eo, so);

        // ---- outer product via smem (store in value order) ----
        *stOut = p_out;              // [32..47]=psl, [48..63]=psh (natural order)
        __syncwarp();
        float4 o0 = po4[0];
        float4 o1 = po4[1];
        float hvv = *pshp;           // psh[lane>>1]
        o0.x *= hvv;  o0.y *= hvv;  o0.z *= hvv;  o0.w *= hvv;
        o1.x *= hvv;  o1.y *= hvv;  o1.z *= hvv;  o1.w *= hvv;
        ((float4*)(orow + i * 256))[0] = o0;
        ((float4*)(orow + i * 256))[1] = o1;
    }
}

extern "C" void kernel_launch(void* const* d_in, const int* in_sizes, int n_in,
                              void* d_out, int out_size) {
    const float* A  = (const float*)d_in[0];
    const float* Bq = (const float*)d_in[1];
    float* O = (float*)d_out;
    int B = in_sizes[0] / 1024;          // [B, 4, 256]
    dim3 grid((B + 7) / 8);
    nalu_kernel<<<grid, 256>>>(A, Bq, O, B);
}